// round 3
// baseline (speedup 1.0000x reference)
#include <cuda_runtime.h>
#include <math.h>

#define BB     8
#define RDIM   64
#define CDIM   16
#define DDIM   128
#define NPAIR  2016
#define PPB    8
#define NGRP   (NPAIR / PPB)   // 252
#define NT     512
#define AP     132             // padded activation pitch (floats)

// scale = 1/sqrt(D*C) = 1/sqrt(2048)
#define SCALE  0.022097086912079608f

// scratch: k = batch_input @ kW + kb  (B,R,C,D) fp32 = 4MB
__device__ float g_k[BB * RDIM * CDIM * DDIM];

// ---------------------------------------------------------------------------
// Kernel 1: K projection. One block per (b,r) row-group: 16x128 @ 128x128.
// ---------------------------------------------------------------------------
__global__ __launch_bounds__(256) void k_proj_kernel(
    const float* __restrict__ bi, const float* __restrict__ kW,
    const float* __restrict__ kb)
{
    extern __shared__ float sm1[];
    float* sx = sm1;             // 16*128 = 2048 floats
    float* sw = sm1 + 2048;      // 128*128 = 16384 floats
    const int br = blockIdx.x;   // 0..B*R-1
    const int t  = threadIdx.x;

    const float4* src = (const float4*)(bi + (size_t)br * CDIM * DDIM);
    for (int i = t; i < (CDIM * DDIM) / 4; i += 256) ((float4*)sx)[i] = src[i];
    for (int i = t; i < (DDIM * DDIM) / 4; i += 256) ((float4*)sw)[i] = ((const float4*)kW)[i];
    __syncthreads();

    const int rw = t >> 4;          // 0..15
    const int j0 = (t & 15) * 8;    // 0..120

    float acc[8] = {0.f,0.f,0.f,0.f,0.f,0.f,0.f,0.f};
    #pragma unroll 4
    for (int k = 0; k < DDIM; ++k) {
        float a = sx[rw * DDIM + k];
        float4 w0 = *(const float4*)&sw[k * DDIM + j0];
        float4 w1 = *(const float4*)&sw[k * DDIM + j0 + 4];
        acc[0] += a * w0.x; acc[1] += a * w0.y; acc[2] += a * w0.z; acc[3] += a * w0.w;
        acc[4] += a * w1.x; acc[5] += a * w1.y; acc[6] += a * w1.z; acc[7] += a * w1.w;
    }
    float4 b0 = *(const float4*)&kb[j0];
    float4 b1 = *(const float4*)&kb[j0 + 4];
    float* dst = g_k + (size_t)br * CDIM * DDIM + rw * DDIM + j0;
    *(float4*)(dst)     = make_float4(acc[0]+b0.x, acc[1]+b0.y, acc[2]+b0.z, acc[3]+b0.w);
    *(float4*)(dst + 4) = make_float4(acc[4]+b1.x, acc[5]+b1.y, acc[6]+b1.z, acc[7]+b1.w);
}

// ---------------------------------------------------------------------------
// Register-tiled 128x128x128 GEMM from shared memory.
// A: [128][AP] row-major activations, W: [128][128] row-major weights.
// Thread (i0 = (t>>4)*4 rows, j0 = (t&15)*8 cols) computes a 4x8 tile.
// ---------------------------------------------------------------------------
__device__ __forceinline__ void gemm_tile(const float* __restrict__ A,
                                          const float* __restrict__ W,
                                          int i0, int j0, float acc[4][8])
{
    #pragma unroll
    for (int ii = 0; ii < 4; ++ii)
        #pragma unroll
        for (int jj = 0; jj < 8; ++jj) acc[ii][jj] = 0.f;

    for (int kk = 0; kk < DDIM; kk += 4) {
        float4 a4[4];
        #pragma unroll
        for (int ii = 0; ii < 4; ++ii)
            a4[ii] = *(const float4*)&A[(i0 + ii) * AP + kk];
        #pragma unroll
        for (int kw = 0; kw < 4; ++kw) {
            float4 w0 = *(const float4*)&W[(kk + kw) * DDIM + j0];
            float4 w1 = *(const float4*)&W[(kk + kw) * DDIM + j0 + 4];
            #pragma unroll
            for (int ii = 0; ii < 4; ++ii) {
                float a = ((const float*)&a4[ii])[kw];
                acc[ii][0] += a * w0.x; acc[ii][1] += a * w0.y;
                acc[ii][2] += a * w0.z; acc[ii][3] += a * w0.w;
                acc[ii][4] += a * w1.x; acc[ii][5] += a * w1.y;
                acc[ii][6] += a * w1.z; acc[ii][7] += a * w1.w;
            }
        }
    }
}

__device__ __forceinline__ float warp_sum(float v)
{
    v += __shfl_xor_sync(0xffffffffu, v, 16);
    v += __shfl_xor_sync(0xffffffffu, v, 8);
    v += __shfl_xor_sync(0xffffffffu, v, 4);
    v += __shfl_xor_sync(0xffffffffu, v, 2);
    v += __shfl_xor_sync(0xffffffffu, v, 1);
    return v;
}

// ---------------------------------------------------------------------------
// Kernel 2: fully fused per-(batch, 8-pair-group) pipeline.
// ---------------------------------------------------------------------------
__global__ __launch_bounds__(NT, 1) void phylo_kernel(
    const float* __restrict__ bi,   const float* __restrict__ seq_mask,
    const int*   __restrict__ rowA, const int*   __restrict__ colA,
    const float* __restrict__ hW,   const float* __restrict__ hb,
    const float* __restrict__ gW,   const float* __restrict__ gb,
    const float* __restrict__ qW,   const float* __restrict__ qb,
    const float* __restrict__ s1W,  const float* __restrict__ s1b,
    const float* __restrict__ s2W,  const float* __restrict__ s2b,
    float* __restrict__ out)
{
    extern __shared__ float sm[];
    float* sW     = sm;                    // 16384 floats (current weight)
    float* sA     = sm + 16384;            // 128*AP
    float* sB     = sA + 128 * AP;         // 128*AP
    float* salpha = sB + 128 * AP;         // 8*64
    int*   srow   = (int*)(salpha + 8 * 64);
    int*   scol   = srow + 8;

    const int t    = threadIdx.x;
    const int b    = blockIdx.y;
    const int pg0  = blockIdx.x * PPB;
    const int warp = t >> 5;
    const int lane = t & 31;

    if (t < PPB) { srow[t] = rowA[pg0 + t]; scol[t] = colA[pg0 + t]; }
    for (int i = t; i < 4096; i += NT) ((float4*)sW)[i] = ((const float4*)hW)[i];
    __syncthreads();

    // Load diff = x_i - x_j into sA, x_j into sB  (rows: p*16 + c, cols: d)
    for (int idx = t; idx < 4096; idx += NT) {
        int i  = idx >> 5;        // row 0..127
        int d4 = idx & 31;        // float4 index 0..31
        int p  = i >> 4, c = i & 15;
        const float4 xi = *((const float4*)(bi + (((size_t)b * RDIM + srow[p]) * CDIM + c) * DDIM) + d4);
        const float4 xj = *((const float4*)(bi + (((size_t)b * RDIM + scol[p]) * CDIM + c) * DDIM) + d4);
        *(float4*)&sA[i * AP + d4 * 4] = make_float4(xi.x - xj.x, xi.y - xj.y, xi.z - xj.z, xi.w - xj.w);
        *(float4*)&sB[i * AP + d4 * 4] = xj;
    }
    __syncthreads();

    const int i0 = (t >> 4) * 4;
    const int j0 = (t & 15) * 8;
    float acc[4][8];

    // ---- P1: h = diff @ hW + hb ; z = sigmoid(h) ; x = x_j + z*diff -> sB
    gemm_tile(sA, sW, i0, j0, acc);
    {
        float4 b0 = *(const float4*)&hb[j0];
        float4 b1 = *(const float4*)&hb[j0 + 4];
        float bias[8] = {b0.x,b0.y,b0.z,b0.w,b1.x,b1.y,b1.z,b1.w};
        #pragma unroll
        for (int ii = 0; ii < 4; ++ii) {
            int i = i0 + ii;
            float4 dA0 = *(float4*)&sA[i * AP + j0];
            float4 dA1 = *(float4*)&sA[i * AP + j0 + 4];
            float4 xB0 = *(float4*)&sB[i * AP + j0];
            float4 xB1 = *(float4*)&sB[i * AP + j0 + 4];
            float dv[8] = {dA0.x,dA0.y,dA0.z,dA0.w,dA1.x,dA1.y,dA1.z,dA1.w};
            float xv[8] = {xB0.x,xB0.y,xB0.z,xB0.w,xB1.x,xB1.y,xB1.z,xB1.w};
            float r[8];
            #pragma unroll
            for (int jj = 0; jj < 8; ++jj) {
                float h = acc[ii][jj] + bias[jj];
                float z = 1.f / (1.f + __expf(-h));
                r[jj] = xv[jj] + z * dv[jj];
            }
            *(float4*)&sB[i * AP + j0]     = make_float4(r[0], r[1], r[2], r[3]);
            *(float4*)&sB[i * AP + j0 + 4] = make_float4(r[4], r[5], r[6], r[7]);
        }
    }
    __syncthreads();
    for (int i = t; i < 4096; i += NT) ((float4*)sW)[i] = ((const float4*)qW)[i];
    __syncthreads();

    // ---- P2: q = x @ qW + qb -> sA
    gemm_tile(sB, sW, i0, j0, acc);
    {
        float4 b0 = *(const float4*)&qb[j0];
        float4 b1 = *(const float4*)&qb[j0 + 4];
        float bias[8] = {b0.x,b0.y,b0.z,b0.w,b1.x,b1.y,b1.z,b1.w};
        #pragma unroll
        for (int ii = 0; ii < 4; ++ii) {
            int i = i0 + ii;
            float r[8];
            #pragma unroll
            for (int jj = 0; jj < 8; ++jj) r[jj] = acc[ii][jj] + bias[jj];
            *(float4*)&sA[i * AP + j0]     = make_float4(r[0], r[1], r[2], r[3]);
            *(float4*)&sA[i * AP + j0 + 4] = make_float4(r[4], r[5], r[6], r[7]);
        }
    }
    __syncthreads();

    // ---- P3: alpha[p][r] = scale * <q_p, k_r>  (warp handles 4 r's, all 8 p's)
    {
        float accA[8][4];
        #pragma unroll
        for (int p = 0; p < 8; ++p)
            #pragma unroll
            for (int rr = 0; rr < 4; ++rr) accA[p][rr] = 0.f;

        const int r0 = warp * 4;
        for (int c = 0; c < CDIM; ++c) {
            float4 q4[8];
            #pragma unroll
            for (int p = 0; p < 8; ++p)
                q4[p] = *(const float4*)&sA[(p * 16 + c) * AP + lane * 4];
            float4 k4[4];
            #pragma unroll
            for (int rr = 0; rr < 4; ++rr)
                k4[rr] = *(const float4*)&g_k[(((size_t)b * RDIM + r0 + rr) * CDIM + c) * DDIM + lane * 4];
            #pragma unroll
            for (int p = 0; p < 8; ++p)
                #pragma unroll
                for (int rr = 0; rr < 4; ++rr)
                    accA[p][rr] += q4[p].x * k4[rr].x + q4[p].y * k4[rr].y
                                 + q4[p].z * k4[rr].z + q4[p].w * k4[rr].w;
        }
        #pragma unroll
        for (int p = 0; p < 8; ++p)
            #pragma unroll
            for (int rr = 0; rr < 4; ++rr) {
                float v = warp_sum(accA[p][rr]);
                if (lane == 0) salpha[p * 64 + r0 + rr] = v * SCALE;
            }
    }
    __syncthreads();

    // ---- P4: masked softmax over r (warp w = pair w)
    if (warp < 8) {
        int p  = warp;
        int rI = srow[p], cI = scol[p];
        float v0 = salpha[p * 64 + lane];
        float v1 = salpha[p * 64 + 32 + lane];
        if (lane == rI      || lane == cI)      v0 = -INFINITY;
        if (lane + 32 == rI || lane + 32 == cI) v1 = -INFINITY;
        float m = fmaxf(v0, v1);
        #pragma unroll
        for (int off = 16; off > 0; off >>= 1)
            m = fmaxf(m, __shfl_xor_sync(0xffffffffu, m, off));
        float e0 = __expf(v0 - m), e1 = __expf(v1 - m);
        float s = warp_sum(e0 + e1);
        float inv = 1.f / s;
        salpha[p * 64 + lane]      = e0 * inv;
        salpha[p * 64 + 32 + lane] = e1 * inv;
    }
    __syncthreads();

    // ---- P5: x_glob[p][c][d] = sum_r alpha[p][r] * bi[b][r][c][d] -> sA
    {
        int c  = t >> 5;        // warp -> c (16 warps, 16 c's)
        int d0 = lane * 4;
        float4 accG[8];
        #pragma unroll
        for (int p = 0; p < 8; ++p) accG[p] = make_float4(0.f, 0.f, 0.f, 0.f);
        for (int r = 0; r < RDIM; ++r) {
            float4 bv = *(const float4*)&bi[(((size_t)b * RDIM + r) * CDIM + c) * DDIM + d0];
            #pragma unroll
            for (int p = 0; p < 8; ++p) {
                float al = salpha[p * 64 + r];
                accG[p].x += al * bv.x; accG[p].y += al * bv.y;
                accG[p].z += al * bv.z; accG[p].w += al * bv.w;
            }
        }
        #pragma unroll
        for (int p = 0; p < 8; ++p)
            *(float4*)&sA[(p * 16 + c) * AP + d0] = accG[p];
    }
    __syncthreads();
    for (int i = t; i < 4096; i += NT) ((float4*)sW)[i] = ((const float4*)gW)[i];
    __syncthreads();

    // ---- P6: g = x_glob @ gW + gb ; w = sigmoid ; x = x + w*(x_glob - x) -> sB
    gemm_tile(sA, sW, i0, j0, acc);
    {
        float4 b0 = *(const float4*)&gb[j0];
        float4 b1 = *(const float4*)&gb[j0 + 4];
        float bias[8] = {b0.x,b0.y,b0.z,b0.w,b1.x,b1.y,b1.z,b1.w};
        #pragma unroll
        for (int ii = 0; ii < 4; ++ii) {
            int i = i0 + ii;
            float4 gA0 = *(float4*)&sA[i * AP + j0];
            float4 gA1 = *(float4*)&sA[i * AP + j0 + 4];
            float4 xB0 = *(float4*)&sB[i * AP + j0];
            float4 xB1 = *(float4*)&sB[i * AP + j0 + 4];
            float gv[8] = {gA0.x,gA0.y,gA0.z,gA0.w,gA1.x,gA1.y,gA1.z,gA1.w};
            float xv[8] = {xB0.x,xB0.y,xB0.z,xB0.w,xB1.x,xB1.y,xB1.z,xB1.w};
            float r[8];
            #pragma unroll
            for (int jj = 0; jj < 8; ++jj) {
                float g  = acc[ii][jj] + bias[jj];
                float wv = 1.f / (1.f + __expf(-g));
                r[jj] = xv[jj] + wv * (gv[jj] - xv[jj]);
            }
            *(float4*)&sB[i * AP + j0]     = make_float4(r[0], r[1], r[2], r[3]);
            *(float4*)&sB[i * AP + j0 + 4] = make_float4(r[4], r[5], r[6], r[7]);
        }
    }
    __syncthreads();
    for (int i = t; i < 4096; i += NT) ((float4*)sW)[i] = ((const float4*)s1W)[i];
    __syncthreads();

    // ---- P7: u = gelu_exact(x @ s1W + s1b) -> sA
    gemm_tile(sB, sW, i0, j0, acc);
    {
        float4 b0 = *(const float4*)&s1b[j0];
        float4 b1 = *(const float4*)&s1b[j0 + 4];
        float bias[8] = {b0.x,b0.y,b0.z,b0.w,b1.x,b1.y,b1.z,b1.w};
        #pragma unroll
        for (int ii = 0; ii < 4; ++ii) {
            int i = i0 + ii;
            float r[8];
            #pragma unroll
            for (int jj = 0; jj < 8; ++jj) {
                float u = acc[ii][jj] + bias[jj];
                r[jj] = 0.5f * u * (1.f + erff(u * 0.70710678118654752f));
            }
            *(float4*)&sA[i * AP + j0]     = make_float4(r[0], r[1], r[2], r[3]);
            *(float4*)&sA[i * AP + j0 + 4] = make_float4(r[4], r[5], r[6], r[7]);
        }
    }
    __syncthreads();

    // ---- P8: s = u @ s2W + s2b ; score = sum_c s[c] * seq_mask[b][c]
    if (warp < 8) {
        int p = warp;
        float4 w2 = *(const float4*)&s2W[lane * 4];
        float s2b0 = s2b[0];
        float total = 0.f;
        #pragma unroll
        for (int c = 0; c < CDIM; ++c) {
            float4 u4 = *(const float4*)&sA[(p * 16 + c) * AP + lane * 4];
            float part = u4.x * w2.x + u4.y * w2.y + u4.z * w2.z + u4.w * w2.w;
            part = warp_sum(part);
            total += (part + s2b0) * seq_mask[b * CDIM + c];
        }
        if (lane == 0) out[b * NPAIR + pg0 + p] = total;
    }
}

// ---------------------------------------------------------------------------
extern "C" void kernel_launch(void* const* d_in, const int* in_sizes, int n_in,
                              void* d_out, int out_size)
{
    (void)in_sizes; (void)n_in; (void)out_size;
    const float* bi       = (const float*)d_in[0];
    const float* seq_mask = (const float*)d_in[1];
    const int*   rowA     = (const int*)  d_in[2];
    const int*   colA     = (const int*)  d_in[3];
    const float* hW  = (const float*)d_in[4];
    const float* hb  = (const float*)d_in[5];
    const float* gW  = (const float*)d_in[6];
    const float* gb  = (const float*)d_in[7];
    const float* qW  = (const float*)d_in[8];
    const float* qb  = (const float*)d_in[9];
    const float* kW  = (const float*)d_in[10];
    const float* kb  = (const float*)d_in[11];
    const float* s1W = (const float*)d_in[12];
    const float* s1b = (const float*)d_in[13];
    const float* s2W = (const float*)d_in[14];
    const float* s2b = (const float*)d_in[15];
    float* out = (float*)d_out;

    const size_t ksmem = (2048 + 16384) * sizeof(float);                   // 72 KB
    const size_t msmem = (16384 + 2 * 128 * AP + 8 * 64) * sizeof(float)
                       + 16 * sizeof(int);                                  // ~203 KB

    cudaFuncSetAttribute(k_proj_kernel, cudaFuncAttributeMaxDynamicSharedMemorySize, (int)ksmem);
    cudaFuncSetAttribute(phylo_kernel,  cudaFuncAttributeMaxDynamicSharedMemorySize, (int)msmem);

    k_proj_kernel<<<BB * RDIM, 256, ksmem>>>(bi, kW, kb);
    phylo_kernel<<<dim3(NGRP, BB), NT, msmem>>>(
        bi, seq_mask, rowA, colA,
        hW, hb, gW, gb, qW, qb, s1W, s1b, s2W, s2b, out);
}

// round 8
// speedup vs baseline: 2.0620x; 2.0620x over previous
#include <cuda_runtime.h>
#include <math.h>
#include <stdint.h>

#define BB     8
#define RDIM   64
#define CDIM   16
#define DDIM   128
#define NPAIR  2016
#define PPB    8
#define NGRP   (NPAIR / PPB)   // 252
#define NT     512
#define AP     132             // padded pitch (floats)

// scale = 1/sqrt(D*C) = 1/sqrt(2048)
#define SCALE  0.022097086912079608f

__device__ float g_k [BB * RDIM * CDIM * DDIM];   // K projection (4MB)
__device__ float g_wt[4 * DDIM * DDIM];           // W^T (tf32-rounded): hW,qW,gW,s1W

// ---------------------------------------------------------------------------
static __device__ __forceinline__ uint32_t rna_tf32(float v) {
    uint32_t r;
    asm("cvt.rna.tf32.f32 %0, %1;" : "=r"(r) : "f"(v));
    return r;
}

static __device__ __forceinline__ void mma8(float c[4], const uint32_t a[4],
                                            const uint32_t b[2]) {
    asm volatile(
        "mma.sync.aligned.m16n8k8.row.col.f32.tf32.tf32.f32 "
        "{%0,%1,%2,%3}, {%4,%5,%6,%7}, {%8,%9}, {%0,%1,%2,%3};"
        : "+f"(c[0]), "+f"(c[1]), "+f"(c[2]), "+f"(c[3])
        : "r"(a[0]), "r"(a[1]), "r"(a[2]), "r"(a[3]), "r"(b[0]), "r"(b[1]));
}

__device__ __forceinline__ float warp_sum(float v) {
    v += __shfl_xor_sync(0xffffffffu, v, 16);
    v += __shfl_xor_sync(0xffffffffu, v, 8);
    v += __shfl_xor_sync(0xffffffffu, v, 4);
    v += __shfl_xor_sync(0xffffffffu, v, 2);
    v += __shfl_xor_sync(0xffffffffu, v, 1);
    return v;
}

// ---------------------------------------------------------------------------
// Warp-tiled 128x128x128 tf32 GEMM: D = Act @ W  (W given as W^T rows in sWgt).
// Warp (4x4 grid) computes a 32x32 tile: 2 m-tiles (16) x 4 n-tiles (8).
// acc[mt][nt][0..3] per mma fragment layout.
// ---------------------------------------------------------------------------
__device__ __forceinline__ void mma_gemm(const float* __restrict__ sAct,
                                         const float* __restrict__ sWgt,
                                         int mrow, int ncol, int gid, int tig,
                                         float acc[2][4][4])
{
    #pragma unroll
    for (int mt = 0; mt < 2; ++mt)
        #pragma unroll
        for (int nt = 0; nt < 4; ++nt)
            #pragma unroll
            for (int q = 0; q < 4; ++q) acc[mt][nt][q] = 0.f;

    #pragma unroll 2
    for (int k0 = 0; k0 < DDIM; k0 += 8) {
        uint32_t a[2][4], bf[4][2];
        #pragma unroll
        for (int mt = 0; mt < 2; ++mt) {
            const float* base = sAct + (mrow + mt * 16 + gid) * AP + k0 + tig;
            a[mt][0] = rna_tf32(base[0]);
            a[mt][1] = rna_tf32(base[8 * AP]);
            a[mt][2] = rna_tf32(base[4]);
            a[mt][3] = rna_tf32(base[8 * AP + 4]);
        }
        #pragma unroll
        for (int nt = 0; nt < 4; ++nt) {
            const float* base = sWgt + (ncol + nt * 8 + gid) * AP + k0 + tig;
            bf[nt][0] = __float_as_uint(base[0]);   // pre-rounded
            bf[nt][1] = __float_as_uint(base[4]);
        }
        #pragma unroll
        for (int mt = 0; mt < 2; ++mt)
            #pragma unroll
            for (int nt = 0; nt < 4; ++nt)
                mma8(acc[mt][nt], a[mt], bf[nt]);
    }
}

// ---------------------------------------------------------------------------
// Kernel 0: transpose + tf32-round the 4 weights into g_wt  (WT[n][k]=W[k][n])
// ---------------------------------------------------------------------------
__global__ __launch_bounds__(256) void wt_kernel(
    const float* __restrict__ hW, const float* __restrict__ qW,
    const float* __restrict__ gW, const float* __restrict__ s1W)
{
    extern __shared__ float tile[];   // 128*129
    const float* W = (blockIdx.x == 0) ? hW : (blockIdx.x == 1) ? qW
                   : (blockIdx.x == 2) ? gW : s1W;
    const int t = threadIdx.x;
    for (int i = t; i < DDIM * DDIM; i += 256) {
        int k = i >> 7, n = i & 127;
        tile[k * 129 + n] = W[i];
    }
    __syncthreads();
    float* dst = g_wt + (size_t)blockIdx.x * DDIM * DDIM;
    for (int i = t; i < DDIM * DDIM; i += 256) {
        int n = i >> 7, k = i & 127;
        dst[i] = __uint_as_float(rna_tf32(tile[k * 129 + n]));
    }
}

// ---------------------------------------------------------------------------
// Kernel 1: K projection (scalar fp32; exact)
// ---------------------------------------------------------------------------
__global__ __launch_bounds__(256) void k_proj_kernel(
    const float* __restrict__ bi, const float* __restrict__ kW,
    const float* __restrict__ kb)
{
    extern __shared__ float sm1[];
    float* sx = sm1;             // 16*128
    float* sw = sm1 + 2048;      // 128*128
    const int br = blockIdx.x;
    const int t  = threadIdx.x;

    const float4* src = (const float4*)(bi + (size_t)br * CDIM * DDIM);
    for (int i = t; i < (CDIM * DDIM) / 4; i += 256) ((float4*)sx)[i] = src[i];
    for (int i = t; i < (DDIM * DDIM) / 4; i += 256) ((float4*)sw)[i] = ((const float4*)kW)[i];
    __syncthreads();

    const int rw = t >> 4;
    const int j0 = (t & 15) * 8;

    float acc[8] = {0.f,0.f,0.f,0.f,0.f,0.f,0.f,0.f};
    #pragma unroll 4
    for (int k = 0; k < DDIM; ++k) {
        float a = sx[rw * DDIM + k];
        float4 w0 = *(const float4*)&sw[k * DDIM + j0];
        float4 w1 = *(const float4*)&sw[k * DDIM + j0 + 4];
        acc[0] += a * w0.x; acc[1] += a * w0.y; acc[2] += a * w0.z; acc[3] += a * w0.w;
        acc[4] += a * w1.x; acc[5] += a * w1.y; acc[6] += a * w1.z; acc[7] += a * w1.w;
    }
    float4 b0 = *(const float4*)&kb[j0];
    float4 b1 = *(const float4*)&kb[j0 + 4];
    float* dst = g_k + (size_t)br * CDIM * DDIM + rw * DDIM + j0;
    *(float4*)(dst)     = make_float4(acc[0]+b0.x, acc[1]+b0.y, acc[2]+b0.z, acc[3]+b0.w);
    *(float4*)(dst + 4) = make_float4(acc[4]+b1.x, acc[5]+b1.y, acc[6]+b1.z, acc[7]+b1.w);
}

// ---------------------------------------------------------------------------
// Kernel 2: fused per-(batch, 8-pair) pipeline; GEMMs via tf32 mma.sync
// ---------------------------------------------------------------------------
__global__ __launch_bounds__(NT, 1) void phylo_kernel(
    const float* __restrict__ bi,   const float* __restrict__ seq_mask,
    const int*   __restrict__ rowA, const int*   __restrict__ colA,
    const float* __restrict__ hb,   const float* __restrict__ gb,
    const float* __restrict__ qb,   const float* __restrict__ s1b,
    const float* __restrict__ s2W,  const float* __restrict__ s2b,
    float* __restrict__ out)
{
    extern __shared__ __align__(16) float sm[];
    float* sW = sm;                    // 128*AP  (W^T staged, tf32-rounded)
    float* sA = sW + 128 * AP;         // 128*AP
    float* sB = sA + 128 * AP;         // 128*AP
    __shared__ float salpha[PPB * RDIM];
    __shared__ int   srow[PPB], scol[PPB];

    const int t    = threadIdx.x;
    const int b    = blockIdx.y;
    const int pg0  = blockIdx.x * PPB;
    const int warp = t >> 5;
    const int lane = t & 31;
    const int gid  = lane >> 2;        // 0..7
    const int tig  = lane & 3;         // 0..3
    const int mrow = (warp >> 2) * 32;
    const int ncol = (warp & 3) * 32;

    if (t < PPB) { srow[t] = rowA[pg0 + t]; scol[t] = colA[pg0 + t]; }
    // stage hW^T
    for (int i = t; i < 4096; i += NT) {
        int n = i >> 5, k4 = i & 31;
        *(float4*)&sW[n * AP + k4 * 4] = ((const float4*)g_wt)[i];
    }
    __syncthreads();

    // sA = diff = x_i - x_j ; sB = x_j   (rows: p*16+c)
    for (int idx = t; idx < 4096; idx += NT) {
        int row = idx >> 5, d4 = idx & 31;
        int p = row >> 4, c = row & 15;
        const float4 xi = *((const float4*)(bi + (((size_t)b * RDIM + srow[p]) * CDIM + c) * DDIM) + d4);
        const float4 xj = *((const float4*)(bi + (((size_t)b * RDIM + scol[p]) * CDIM + c) * DDIM) + d4);
        *(float4*)&sA[row * AP + d4 * 4] = make_float4(xi.x - xj.x, xi.y - xj.y,
                                                       xi.z - xj.z, xi.w - xj.w);
        *(float4*)&sB[row * AP + d4 * 4] = xj;
    }
    __syncthreads();

    float acc[2][4][4];

    // ===== G1: h = diff @ hW + hb ; x = xj + sigmoid(h)*diff -> sB ==========
    mma_gemm(sA, sW, mrow, ncol, gid, tig, acc);
    #pragma unroll
    for (int nt = 0; nt < 4; ++nt) {
        int cc = ncol + nt * 8 + 2 * tig;
        float2 bb = *(const float2*)&hb[cc];
        #pragma unroll
        for (int mt = 0; mt < 2; ++mt) {
            #pragma unroll
            for (int h = 0; h < 2; ++h) {
                int row = mrow + mt * 16 + gid + 8 * h;
                float2 dv = *(float2*)&sA[row * AP + cc];
                float2 xv = *(float2*)&sB[row * AP + cc];
                float h0 = acc[mt][nt][2*h]   + bb.x;
                float h1 = acc[mt][nt][2*h+1] + bb.y;
                float z0 = 1.f / (1.f + __expf(-h0));
                float z1 = 1.f / (1.f + __expf(-h1));
                *(float2*)&sB[row * AP + cc] =
                    make_float2(xv.x + z0 * dv.x, xv.y + z1 * dv.y);
            }
        }
    }
    __syncthreads();
    for (int i = t; i < 4096; i += NT) {
        int n = i >> 5, k4 = i & 31;
        *(float4*)&sW[n * AP + k4 * 4] = ((const float4*)(g_wt + DDIM * DDIM))[i];
    }
    __syncthreads();

    // ===== G2: q = x @ qW + qb -> sA ========================================
    mma_gemm(sB, sW, mrow, ncol, gid, tig, acc);
    #pragma unroll
    for (int nt = 0; nt < 4; ++nt) {
        int cc = ncol + nt * 8 + 2 * tig;
        float2 bb = *(const float2*)&qb[cc];
        #pragma unroll
        for (int mt = 0; mt < 2; ++mt) {
            #pragma unroll
            for (int h = 0; h < 2; ++h) {
                int row = mrow + mt * 16 + gid + 8 * h;
                *(float2*)&sA[row * AP + cc] =
                    make_float2(acc[mt][nt][2*h] + bb.x, acc[mt][nt][2*h+1] + bb.y);
            }
        }
    }
    __syncthreads();

    // ===== P3: alpha[p][r] = scale * <q_p, k_r> =============================
    {
        float accA[8][4];
        #pragma unroll
        for (int p = 0; p < 8; ++p)
            #pragma unroll
            for (int rr = 0; rr < 4; ++rr) accA[p][rr] = 0.f;
        const int r0 = warp * 4;
        for (int c = 0; c < CDIM; ++c) {
            float4 q4[8];
            #pragma unroll
            for (int p = 0; p < 8; ++p)
                q4[p] = *(const float4*)&sA[(p * 16 + c) * AP + lane * 4];
            float4 k4[4];
            #pragma unroll
            for (int rr = 0; rr < 4; ++rr)
                k4[rr] = *(const float4*)&g_k[(((size_t)b * RDIM + r0 + rr) * CDIM + c) * DDIM + lane * 4];
            #pragma unroll
            for (int p = 0; p < 8; ++p)
                #pragma unroll
                for (int rr = 0; rr < 4; ++rr)
                    accA[p][rr] += q4[p].x * k4[rr].x + q4[p].y * k4[rr].y
                                 + q4[p].z * k4[rr].z + q4[p].w * k4[rr].w;
        }
        #pragma unroll
        for (int p = 0; p < 8; ++p)
            #pragma unroll
            for (int rr = 0; rr < 4; ++rr) {
                float v = warp_sum(accA[p][rr]);
                if (lane == 0) salpha[p * 64 + r0 + rr] = v * SCALE;
            }
    }
    __syncthreads();

    // ===== P4: masked softmax over r =========================================
    if (warp < 8) {
        int p  = warp;
        int rI = srow[p], cI = scol[p];
        float v0 = salpha[p * 64 + lane];
        float v1 = salpha[p * 64 + 32 + lane];
        if (lane == rI      || lane == cI)      v0 = -INFINITY;
        if (lane + 32 == rI || lane + 32 == cI) v1 = -INFINITY;
        float mx = fmaxf(v0, v1);
        #pragma unroll
        for (int off = 16; off > 0; off >>= 1)
            mx = fmaxf(mx, __shfl_xor_sync(0xffffffffu, mx, off));
        float e0 = __expf(v0 - mx), e1 = __expf(v1 - mx);
        float s = warp_sum(e0 + e1);
        float inv = 1.f / s;
        salpha[p * 64 + lane]      = e0 * inv;
        salpha[p * 64 + 32 + lane] = e1 * inv;
    }
    __syncthreads();

    // ===== P5: x_glob = alpha @ batch_input -> sA ===========================
    {
        int c  = warp;            // 16 warps <-> 16 c
        int d0 = lane * 4;
        float4 accG[8];
        #pragma unroll
        for (int p = 0; p < 8; ++p) accG[p] = make_float4(0.f, 0.f, 0.f, 0.f);
        for (int r = 0; r < RDIM; ++r) {
            float4 bv = *(const float4*)&bi[(((size_t)b * RDIM + r) * CDIM + c) * DDIM + d0];
            #pragma unroll
            for (int p = 0; p < 8; ++p) {
                float al = salpha[p * 64 + r];
                accG[p].x += al * bv.x; accG[p].y += al * bv.y;
                accG[p].z += al * bv.z; accG[p].w += al * bv.w;
            }
        }
        #pragma unroll
        for (int p = 0; p < 8; ++p)
            *(float4*)&sA[(p * 16 + c) * AP + d0] = accG[p];
    }
    __syncthreads();
    for (int i = t; i < 4096; i += NT) {
        int n = i >> 5, k4 = i & 31;
        *(float4*)&sW[n * AP + k4 * 4] = ((const float4*)(g_wt + 2 * DDIM * DDIM))[i];
    }
    __syncthreads();

    // ===== G3: g = x_glob @ gW + gb ; x = x + sig(g)*(x_glob - x) -> sB =====
    mma_gemm(sA, sW, mrow, ncol, gid, tig, acc);
    #pragma unroll
    for (int nt = 0; nt < 4; ++nt) {
        int cc = ncol + nt * 8 + 2 * tig;
        float2 bb = *(const float2*)&gb[cc];
        #pragma unroll
        for (int mt = 0; mt < 2; ++mt) {
            #pragma unroll
            for (int h = 0; h < 2; ++h) {
                int row = mrow + mt * 16 + gid + 8 * h;
                float2 gv = *(float2*)&sA[row * AP + cc];
                float2 xv = *(float2*)&sB[row * AP + cc];
                float g0 = acc[mt][nt][2*h]   + bb.x;
                float g1 = acc[mt][nt][2*h+1] + bb.y;
                float w0 = 1.f / (1.f + __expf(-g0));
                float w1 = 1.f / (1.f + __expf(-g1));
                *(float2*)&sB[row * AP + cc] =
                    make_float2(xv.x + w0 * (gv.x - xv.x),
                                xv.y + w1 * (gv.y - xv.y));
            }
        }
    }
    __syncthreads();
    for (int i = t; i < 4096; i += NT) {
        int n = i >> 5, k4 = i & 31;
        *(float4*)&sW[n * AP + k4 * 4] = ((const float4*)(g_wt + 3 * DDIM * DDIM))[i];
    }
    __syncthreads();

    // ===== G4: u = gelu_exact(x @ s1W + s1b) -> sA ==========================
    mma_gemm(sB, sW, mrow, ncol, gid, tig, acc);
    const float is2 = 0.70710678118654752f;
    #pragma unroll
    for (int nt = 0; nt < 4; ++nt) {
        int cc = ncol + nt * 8 + 2 * tig;
        float2 bb = *(const float2*)&s1b[cc];
        #pragma unroll
        for (int mt = 0; mt < 2; ++mt) {
            #pragma unroll
            for (int h = 0; h < 2; ++h) {
                int row = mrow + mt * 16 + gid + 8 * h;
                float u0 = acc[mt][nt][2*h]   + bb.x;
                float u1 = acc[mt][nt][2*h+1] + bb.y;
                *(float2*)&sA[row * AP + cc] =
                    make_float2(0.5f * u0 * (1.f + erff(u0 * is2)),
                                0.5f * u1 * (1.f + erff(u1 * is2)));
            }
        }
    }
    __syncthreads();

    // ===== P8: s = u @ s2W + s2b ; masked row-sum ===========================
    if (warp < 8) {
        int p = warp;
        float4 w2 = *(const float4*)&s2W[lane * 4];
        float s2b0 = s2b[0];
        float total = 0.f;
        #pragma unroll
        for (int c = 0; c < CDIM; ++c) {
            float4 u4 = *(const float4*)&sA[(p * 16 + c) * AP + lane * 4];
            float part = u4.x * w2.x + u4.y * w2.y + u4.z * w2.z + u4.w * w2.w;
            part = warp_sum(part);
            total += (part + s2b0) * seq_mask[b * CDIM + c];
        }
        if (lane == 0) out[b * NPAIR + pg0 + p] = total;
    }
}

// ---------------------------------------------------------------------------
extern "C" void kernel_launch(void* const* d_in, const int* in_sizes, int n_in,
                              void* d_out, int out_size)
{
    (void)in_sizes; (void)n_in; (void)out_size;
    const float* bi       = (const float*)d_in[0];
    const float* seq_mask = (const float*)d_in[1];
    const int*   rowA     = (const int*)  d_in[2];
    const int*   colA     = (const int*)  d_in[3];
    const float* hW  = (const float*)d_in[4];
    const float* hb  = (const float*)d_in[5];
    const float* gW  = (const float*)d_in[6];
    const float* gb  = (const float*)d_in[7];
    const float* qW  = (const float*)d_in[8];
    const float* qb  = (const float*)d_in[9];
    const float* kW  = (const float*)d_in[10];
    const float* kb  = (const float*)d_in[11];
    const float* s1W = (const float*)d_in[12];
    const float* s1b = (const float*)d_in[13];
    const float* s2W = (const float*)d_in[14];
    const float* s2b = (const float*)d_in[15];
    float* out = (float*)d_out;

    const size_t tsmem = 128 * 129 * sizeof(float);          // 66KB
    const size_t ksmem = (2048 + 16384) * sizeof(float);     // 72KB
    const size_t msmem = 3 * 128 * AP * sizeof(float);       // ~198KB

    cudaFuncSetAttribute(wt_kernel,     cudaFuncAttributeMaxDynamicSharedMemorySize, (int)tsmem);
    cudaFuncSetAttribute(k_proj_kernel, cudaFuncAttributeMaxDynamicSharedMemorySize, (int)ksmem);
    cudaFuncSetAttribute(phylo_kernel,  cudaFuncAttributeMaxDynamicSharedMemorySize, (int)msmem);

    wt_kernel<<<4, 256, tsmem>>>(hW, qW, gW, s1W);
    k_proj_kernel<<<BB * RDIM, 256, ksmem>>>(bi, kW, kb);
    phylo_kernel<<<dim3(NGRP, BB), NT, msmem>>>(
        bi, seq_mask, rowA, colA,
        hb, gb, qb, s1b, s2W, s2b, out);
}